// round 2
// baseline (speedup 1.0000x reference)
#include <cuda_runtime.h>
#include <cuda_bf16.h>
#include <cstdint>

#define N_BINS 10

// Global accumulators: counts[10], conf_sum[10], acc_sum[10] as doubles.
__device__ double g_acc[3 * N_BINS];

__global__ void rd_zero_kernel() {
    int t = threadIdx.x;
    if (t < 3 * N_BINS) g_acc[t] = 0.0;
}

__global__ void __launch_bounds__(256, 8)
rd_main_kernel(const float4* __restrict__ sm, const int* __restrict__ labels, int N) {
    __shared__ float s_cnt[N_BINS];
    __shared__ float s_conf[N_BINS];
    __shared__ float s_acc[N_BINS];

    const int tid = threadIdx.x;
    if (tid < N_BINS) {
        s_cnt[tid] = 0.0f;
        s_conf[tid] = 0.0f;
        s_acc[tid] = 0.0f;
    }
    __syncthreads();

    const int lane = tid & 31;
    const int warp_global = (blockIdx.x * blockDim.x + tid) >> 5;
    const int n_warps = (gridDim.x * blockDim.x) >> 5;

    for (int row = warp_global; row < N; row += n_warps) {
        // One row = 128 floats = 32 lanes x float4, fully coalesced.
        float4 v = __ldg(&sm[(size_t)row * 32 + lane]);

        // Local max of 4 with first-index tie-break (indices lane*4 + {0..3}).
        float m = v.x; int li = 0;
        if (v.y > m) { m = v.y; li = 1; }
        if (v.z > m) { m = v.z; li = 2; }
        if (v.w > m) { m = v.w; li = 3; }

        // Warp max via redux on bit pattern (values >= 0 => monotonic in uint).
        unsigned mb = __float_as_uint(m);
        unsigned maxb = __reduce_max_sync(0xffffffffu, mb);
        // First lane holding the max has the globally smallest index
        // (index = lane*4 + li is monotonic in lane).
        unsigned ball = __ballot_sync(0xffffffffu, mb == maxb);
        int src = __ffs(ball) - 1;
        int idx4 = __shfl_sync(0xffffffffu, li, src);

        if (lane == 0) {
            float conf = __uint_as_float(maxb);
            int pred = src * 4 + idx4;
            int lab = labels[row];
            float acc = (pred == lab) ? 1.0f : 0.0f;

            int bin = (int)ceilf(conf * 10.0f) - 1;
            bin = max(0, min(N_BINS - 1, bin));

            atomicAdd(&s_cnt[bin], 1.0f);
            atomicAdd(&s_conf[bin], conf);
            atomicAdd(&s_acc[bin], acc);
        }
    }

    __syncthreads();
    if (tid < N_BINS) {
        float c = s_cnt[tid];
        if (c != 0.0f)          atomicAdd(&g_acc[tid],              (double)c);
        float cs = s_conf[tid];
        if (cs != 0.0f)         atomicAdd(&g_acc[N_BINS + tid],     (double)cs);
        float as = s_acc[tid];
        if (as != 0.0f)         atomicAdd(&g_acc[2 * N_BINS + tid], (double)as);
    }
}

__global__ void rd_finalize_kernel(float* __restrict__ out) {
    int i = threadIdx.x;
    if (i < N_BINS) {
        double c = g_acc[i];
        if (c > 0.0) {
            out[i]          = (float)(g_acc[N_BINS + i] / c);       // avg confidence
            out[N_BINS + i] = (float)(g_acc[2 * N_BINS + i] / c);   // accuracy
        } else {
            out[i] = 0.0f;
            out[N_BINS + i] = 0.0f;
        }
    }
}

extern "C" void kernel_launch(void* const* d_in, const int* in_sizes, int n_in,
                              void* d_out, int out_size) {
    const float4* sm = (const float4*)d_in[0];
    const int* labels = (const int*)d_in[1];
    float* out = (float*)d_out;

    const int N = in_sizes[1];  // number of rows (labels count)

    rd_zero_kernel<<<1, 32>>>();

    const int threads = 256;
    const int blocks = 1184;  // 8 blocks/SM on 148 SMs
    rd_main_kernel<<<blocks, threads>>>(sm, labels, N);

    rd_finalize_kernel<<<1, 32>>>(out);
}

// round 6
// speedup vs baseline: 1.4409x; 1.4409x over previous
#include <cuda_runtime.h>
#include <cuda_bf16.h>
#include <cstdint>

#define N_BINS 10
#define UNROLL 4

// Global accumulators: counts[10], conf_sum[10], acc_sum[10] as doubles.
__device__ double g_acc[3 * N_BINS];

__global__ void rd_zero_kernel() {
    int t = threadIdx.x;
    if (t < 3 * N_BINS) g_acc[t] = 0.0;
}

__device__ __forceinline__ void rd_reduce_row(float4 v, int lane, int lab,
                                              float* s_cnt, float* s_conf, float* s_acc) {
    // Local max of 4 with first-index tie-break (indices lane*4 + {0..3}).
    float m = v.x; int li = 0;
    if (v.y > m) { m = v.y; li = 1; }
    if (v.z > m) { m = v.z; li = 2; }
    if (v.w > m) { m = v.w; li = 3; }

    // Warp max via redux on bit pattern (softmax values >= 0 => monotonic in uint).
    unsigned mb = __float_as_uint(m);
    unsigned maxb = __reduce_max_sync(0xffffffffu, mb);
    // Lowest index among lanes holding the max (matches jnp.argmax tie-break).
    unsigned idxc = (mb == maxb) ? (unsigned)(lane * 4 + li) : 0xffffffffu;
    unsigned pred = __reduce_min_sync(0xffffffffu, idxc);

    if (lane == 0) {
        float conf = __uint_as_float(maxb);
        float acc = ((int)pred == lab) ? 1.0f : 0.0f;

        int bin = (int)ceilf(conf * 10.0f) - 1;
        bin = max(0, min(N_BINS - 1, bin));

        atomicAdd(&s_cnt[bin], 1.0f);
        atomicAdd(&s_conf[bin], conf);
        atomicAdd(&s_acc[bin], acc);
    }
}

__global__ void __launch_bounds__(256, 8)
rd_main_kernel(const float4* __restrict__ sm, const int* __restrict__ labels, int N) {
    __shared__ float s_cnt[N_BINS];
    __shared__ float s_conf[N_BINS];
    __shared__ float s_acc[N_BINS];

    const int tid = threadIdx.x;
    if (tid < N_BINS) {
        s_cnt[tid] = 0.0f;
        s_conf[tid] = 0.0f;
        s_acc[tid] = 0.0f;
    }
    __syncthreads();

    const int lane = tid & 31;
    const int warp_global = (blockIdx.x * blockDim.x + tid) >> 5;
    const int n_warps = (gridDim.x * blockDim.x) >> 5;
    const int stride = n_warps * UNROLL;

    int base = warp_global * UNROLL;

    // Fast path: 4 independent LDG.128 issued back-to-back (MLP=4),
    // labels prefetched alongside, reductions run on landed data.
    for (; base + (UNROLL - 1) < N; base += stride) {
        float4 v[UNROLL];
        #pragma unroll
        for (int r = 0; r < UNROLL; r++)
            v[r] = __ldg(&sm[(size_t)(base + r) * 32 + lane]);

        int lab[UNROLL];
        if (lane == 0) {
            #pragma unroll
            for (int r = 0; r < UNROLL; r++)
                lab[r] = labels[base + r];
        }

        #pragma unroll
        for (int r = 0; r < UNROLL; r++)
            rd_reduce_row(v[r], lane, (lane == 0) ? lab[r] : -1, s_cnt, s_conf, s_acc);
    }

    // Tail
    for (; base < N; base++) {
        float4 v = __ldg(&sm[(size_t)base * 32 + lane]);
        int lab = (lane == 0) ? labels[base] : -1;
        rd_reduce_row(v, lane, lab, s_cnt, s_conf, s_acc);
    }

    __syncthreads();
    if (tid < N_BINS) {
        float c = s_cnt[tid];
        if (c != 0.0f)          atomicAdd(&g_acc[tid],              (double)c);
        float cs = s_conf[tid];
        if (cs != 0.0f)         atomicAdd(&g_acc[N_BINS + tid],     (double)cs);
        float as = s_acc[tid];
        if (as != 0.0f)         atomicAdd(&g_acc[2 * N_BINS + tid], (double)as);
    }
}

__global__ void rd_finalize_kernel(float* __restrict__ out) {
    int i = threadIdx.x;
    if (i < N_BINS) {
        double c = g_acc[i];
        if (c > 0.0) {
            out[i]          = (float)(g_acc[N_BINS + i] / c);       // avg confidence
            out[N_BINS + i] = (float)(g_acc[2 * N_BINS + i] / c);   // accuracy
        } else {
            out[i] = 0.0f;
            out[N_BINS + i] = 0.0f;
        }
    }
}

extern "C" void kernel_launch(void* const* d_in, const int* in_sizes, int n_in,
                              void* d_out, int out_size) {
    const float4* sm = (const float4*)d_in[0];
    const int* labels = (const int*)d_in[1];
    float* out = (float*)d_out;

    const int N = in_sizes[1];  // number of rows (labels count)

    rd_zero_kernel<<<1, 32>>>();

    const int threads = 256;
    const int blocks = 1184;  // 8 blocks/SM on 148 SMs
    rd_main_kernel<<<blocks, threads>>>(sm, labels, N);

    rd_finalize_kernel<<<1, 32>>>(out);
}